// round 16
// baseline (speedup 1.0000x reference)
#include <cuda_runtime.h>
#include <cuda_bf16.h>
#include <stdint.h>

// Problem constants (fixed by the dataset)
#define NN 100000      // nodes
#define NE 1600000     // edges
#define NF 256         // input features
#define NH 128         // hidden
#define NC 40          // classes

// ---------------- Scratch (static __device__, no allocations) ----------------
__device__ float g_h1[(size_t)NN * NH];   // GEMM output / agg input
__device__ float g_ha[(size_t)NN * NH];   // agg output / next GEMM input
__device__ int   g_csr[NE];               // CSR src list grouped by dst
__device__ int   g_deg[NN];
__device__ int   g_off[NN];
__device__ int   g_cur[NN];
__device__ float g_dinv[NN];
__device__ int   g_bsum[128];
__device__ int   g_boff[128];
__device__ int   g_e64;                   // 1 if edge_index is int64, 0 if int32

__device__ __forceinline__ float* scratch_buf(int sel) {
    return (sel == 0) ? g_h1 : g_ha;
}

// Edge load honoring detected dtype.
__device__ __forceinline__ int load_edge(const void* ei, long long idx) {
    if (g_e64) return (int)((const long long*)ei)[idx];
    return ((const int*)ei)[idx];
}

// Packed f32x2 helpers (Blackwell base ISA)
#define FMA_F32X2(d, a, b) \
    asm("fma.rn.f32x2 %0, %1, %2, %3;" : "=l"(d) : "l"(a), "l"(b), "l"(d))
#define PACK_DUP(out, x) \
    asm("mov.b64 %0, {%1, %1};" : "=l"(out) : "f"(x))
#define UNPACK2(lo, hi, in) \
    asm("mov.b64 {%0, %1}, %2;" : "=f"(lo), "=f"(hi) : "l"(in))

// ---------------- dtype probe ----------------
// JAX silently downgrades int64->int32 when x64 is disabled (the default).
__global__ void k_detect_dtype(const long long* __restrict__ ei) {
    __shared__ int ok64;
    if (threadIdx.x == 0) ok64 = 1;
    __syncthreads();
    for (int i = threadIdx.x; i < 2048; i += blockDim.x) {
        long long v = ei[i];
        if (v < 0 || v >= (long long)NN) ok64 = 0;
    }
    __syncthreads();
    if (threadIdx.x == 0) g_e64 = ok64;
}

// ---------------- Degree + CSR build ----------------
__global__ void k_zero_deg(int n) {
    int gid = blockIdx.x * blockDim.x + threadIdx.x;
    if (gid < n) g_deg[gid] = 0;
}

__global__ void k_count_deg(const void* __restrict__ ei, int E) {
    int e = blockIdx.x * blockDim.x + threadIdx.x;
    if (e < E) {
        int d = load_edge(ei, (long long)E + e);
        if (d >= 0 && d < NN) atomicAdd(&g_deg[d], 1);
    }
}

__global__ void k_scan_blocks(int n) {
    int tid = threadIdx.x;
    int gid = blockIdx.x * 1024 + tid;
    int lane = tid & 31, wid = tid >> 5;
    int v = (gid < n) ? g_deg[gid] : 0;
    int x = v;
#pragma unroll
    for (int d = 1; d < 32; d <<= 1) {
        int y = __shfl_up_sync(0xffffffffu, x, d);
        if (lane >= d) x += y;
    }
    __shared__ int ws[32];
    if (lane == 31) ws[wid] = x;
    __syncthreads();
    if (wid == 0) {
        int w = ws[lane];
        int t = w;
#pragma unroll
        for (int d = 1; d < 32; d <<= 1) {
            int y = __shfl_up_sync(0xffffffffu, t, d);
            if (lane >= d) t += y;
        }
        ws[lane] = t - w;
    }
    __syncthreads();
    int excl = ws[wid] + x - v;
    if (gid < n) {
        g_off[gid] = excl;
        g_dinv[gid] = rsqrtf((float)v + 1.0f);
    }
    if (tid == 1023) g_bsum[blockIdx.x] = excl + v;
}

__global__ void k_scan_sums(int nb) {
    int tid = threadIdx.x, lane = tid & 31, wid = tid >> 5;
    int v = (tid < nb) ? g_bsum[tid] : 0;
    int x = v;
#pragma unroll
    for (int d = 1; d < 32; d <<= 1) {
        int y = __shfl_up_sync(0xffffffffu, x, d);
        if (lane >= d) x += y;
    }
    __shared__ int ws[4];
    if (lane == 31) ws[wid] = x;
    __syncthreads();
    if (tid == 0) {
        int a = 0;
#pragma unroll
        for (int i = 0; i < 4; i++) { int t = ws[i]; ws[i] = a; a += t; }
    }
    __syncthreads();
    int excl = ws[wid] + x - v;
    if (tid < nb) g_boff[tid] = excl;
}

__global__ void k_scan_add(int n) {
    int gid = blockIdx.x * 1024 + threadIdx.x;
    if (gid < n) {
        int o = g_off[gid] + g_boff[blockIdx.x];
        g_off[gid] = o;
        g_cur[gid] = o;
    }
}

__global__ void k_fill_csr(const void* __restrict__ ei, int E) {
    int e = blockIdx.x * blockDim.x + threadIdx.x;
    if (e < E) {
        int s = load_edge(ei, e);
        int d = load_edge(ei, (long long)E + e);
        if (s >= 0 && s < NN && d >= 0 && d < NN) {
            int p = atomicAdd(&g_cur[d], 1);
            g_csr[p] = s;
        }
    }
}

// ------- f32x2 SGEMM (layers 1-2): C[rows] = [dinv *] (A[rows,K] @ B[K,128]) --
// BM=128, BN=128, BK=16, TM=8, TN=8, 256 threads. (R10-proven structure.)
// Processes row block [row_base + blockIdx.y*BM, ...); bounds vs global M.
template <int K, bool SCALE>
__global__ void __launch_bounds__(256)
sgemm2(const float* __restrict__ Aext, int asel,
       const float* __restrict__ B, int csel, int row_base, int M) {
    constexpr int BM = 128, BN = 128, BK = 16, TM = 8, TN = 8;
    constexpr int THREADS = 256;

    const float* A = (asel < 0) ? Aext : scratch_buf(asel);
    float* C = scratch_buf(csel);

    __shared__ __align__(16) float As[BK][BM + 2];
    __shared__ __align__(16) float Bs[BK][BN];

    const int block_row = row_base + blockIdx.y * BM;
    const int tid = threadIdx.x;
    const int tcol = tid % (BN / TN);   // 0..15
    const int trow = tid / (BN / TN);   // 0..15

    unsigned long long acc[TM][TN / 2];
#pragma unroll
    for (int i = 0; i < TM; i++)
#pragma unroll
        for (int j = 0; j < TN / 2; j++) acc[i][j] = 0ull;

    for (int k0 = 0; k0 < K; k0 += BK) {
        // Load A tile (BM x BK), transposed into As[k][m]
#pragma unroll
        for (int i = tid * 4; i < BM * BK; i += THREADS * 4) {
            int r = i / BK, c = i % BK;
            int row = block_row + r;
            float4 v = make_float4(0.f, 0.f, 0.f, 0.f);
            if (row < M) v = *(const float4*)(A + (size_t)row * K + k0 + c);
            As[c + 0][r] = v.x;
            As[c + 1][r] = v.y;
            As[c + 2][r] = v.z;
            As[c + 3][r] = v.w;
        }
        // Load B tile (BK x BN)
#pragma unroll
        for (int i = tid * 4; i < BK * BN; i += THREADS * 4) {
            int r = i / BN, c = i % BN;
            *(float4*)&Bs[r][c] = *(const float4*)(B + (size_t)(k0 + r) * BN + c);
        }
        __syncthreads();

#pragma unroll
        for (int k = 0; k < BK; k++) {
            unsigned long long a2[TM], b2[TN / 2];
#pragma unroll
            for (int i = 0; i < TM; i++) {
                float ra = As[k][trow * TM + i];
                PACK_DUP(a2[i], ra);
            }
#pragma unroll
            for (int j = 0; j < TN / 2; j++)
                b2[j] = *(const unsigned long long*)&Bs[k][tcol * TN + 2 * j];
#pragma unroll
            for (int i = 0; i < TM; i++)
#pragma unroll
                for (int j = 0; j < TN / 2; j++)
                    FMA_F32X2(acc[i][j], a2[i], b2[j]);
        }
        __syncthreads();
    }

    // Epilogue: optional dinv scale, store
#pragma unroll
    for (int i = 0; i < TM; i++) {
        int row = block_row + trow * TM + i;
        if (row < M) {
            float scale = SCALE ? g_dinv[row] : 1.0f;
            float* crow = C + (size_t)row * NH + tcol * TN;
#pragma unroll
            for (int j = 0; j < TN / 2; j += 2) {
                float4 v;
                UNPACK2(v.x, v.y, acc[i][j]);
                UNPACK2(v.z, v.w, acc[i][j + 1]);
                if (SCALE) { v.x *= scale; v.y *= scale; v.z *= scale; v.w *= scale; }
                *(float4*)(crow + 2 * j) = v;
            }
        }
    }
}

// ---------------- Tiled SGEMM (classifier, R10-proven) ----------------
template <int BM, int BN, int BK, int TM, int TN>
__global__ void sgemm(int asel, const float* __restrict__ B,
                      float* __restrict__ Cext,
                      const float* __restrict__ bias,
                      int row_base, int M, int N, int K) {
    const float* A = scratch_buf(asel);
    float*       C = Cext;

    constexpr int THREADS = (BM / TM) * (BN / TN);
    __shared__ float As[BK][BM + 1];
    __shared__ float Bs[BK][BN];

    const int block_row = row_base + blockIdx.y * BM;
    const int tid = threadIdx.x;
    const int tcol = tid % (BN / TN);
    const int trow = tid / (BN / TN);

    float acc[TM][TN];
#pragma unroll
    for (int i = 0; i < TM; i++)
#pragma unroll
        for (int j = 0; j < TN; j++) acc[i][j] = 0.0f;

    for (int k0 = 0; k0 < K; k0 += BK) {
        for (int i = tid * 4; i < BM * BK; i += THREADS * 4) {
            int r = i / BK, c = i % BK;
            int row = block_row + r;
            float4 v = make_float4(0.f, 0.f, 0.f, 0.f);
            if (row < M) v = *(const float4*)(A + (size_t)row * K + k0 + c);
            As[c + 0][r] = v.x;
            As[c + 1][r] = v.y;
            As[c + 2][r] = v.z;
            As[c + 3][r] = v.w;
        }
        for (int i = tid * 4; i < BK * BN; i += THREADS * 4) {
            int r = i / BN, c = i % BN;
            *(float4*)&Bs[r][c] = *(const float4*)(B + (size_t)(k0 + r) * N + c);
        }
        __syncthreads();

#pragma unroll
        for (int k = 0; k < BK; k++) {
            float ra[TM], rb[TN];
#pragma unroll
            for (int i = 0; i < TM; i++) ra[i] = As[k][trow * TM + i];
#pragma unroll
            for (int j = 0; j < TN; j++) rb[j] = Bs[k][tcol * TN + j];
#pragma unroll
            for (int i = 0; i < TM; i++)
#pragma unroll
                for (int j = 0; j < TN; j++) acc[i][j] += ra[i] * rb[j];
        }
        __syncthreads();
    }

#pragma unroll
    for (int i = 0; i < TM; i++) {
        int row = block_row + trow * TM + i;
        if (row < M) {
#pragma unroll
            for (int j = 0; j < TN; j++) {
                int col = tcol * TN + j;
                C[(size_t)row * N + col] = acc[i][j] + bias[col];
            }
        }
    }
}

// ---------------- Fused aggregation: warp per node, node range [base,base+cnt)
// EDGE_DINV=0 (h pre-scaled): out = relu( dd*(h[i] + Σ h[s]) + b )
// EDGE_DINV=1 (h raw):        out = relu( dd*(dd*h[i] + Σ dinv[s]*h[s]) + b )
template <bool EDGE_DINV>
__global__ void k_aggregate(int hsel, const float* __restrict__ bias,
                            int osel, int base, int count) {
    const float* __restrict__ h = scratch_buf(hsel);
    float* __restrict__ out = scratch_buf(osel);

    int warp = (blockIdx.x * blockDim.x + threadIdx.x) >> 5;
    if (warp >= count) return;
    int lane = threadIdx.x & 31;
    int node = base + warp;

    float dd = g_dinv[node];
    int start = g_off[node];
    int cnt = g_deg[node];

    const float* hb = h + (size_t)lane * 4;

    float4 acc = *(const float4*)(hb + (size_t)node * NH);
    if (EDGE_DINV) { acc.x *= dd; acc.y *= dd; acc.z *= dd; acc.w *= dd; }

    int j = 0;
    for (; j + 4 <= cnt; j += 4) {
        int s0 = g_csr[start + j + 0];
        int s1 = g_csr[start + j + 1];
        int s2 = g_csr[start + j + 2];
        int s3 = g_csr[start + j + 3];
        float4 v0 = *(const float4*)(hb + (size_t)s0 * NH);
        float4 v1 = *(const float4*)(hb + (size_t)s1 * NH);
        float4 v2 = *(const float4*)(hb + (size_t)s2 * NH);
        float4 v3 = *(const float4*)(hb + (size_t)s3 * NH);
        if (EDGE_DINV) {
            float w0 = g_dinv[s0], w1 = g_dinv[s1], w2 = g_dinv[s2], w3 = g_dinv[s3];
            acc.x = fmaf(v0.x, w0, fmaf(v1.x, w1, fmaf(v2.x, w2, fmaf(v3.x, w3, acc.x))));
            acc.y = fmaf(v0.y, w0, fmaf(v1.y, w1, fmaf(v2.y, w2, fmaf(v3.y, w3, acc.y))));
            acc.z = fmaf(v0.z, w0, fmaf(v1.z, w1, fmaf(v2.z, w2, fmaf(v3.z, w3, acc.z))));
            acc.w = fmaf(v0.w, w0, fmaf(v1.w, w1, fmaf(v2.w, w2, fmaf(v3.w, w3, acc.w))));
        } else {
            acc.x += (v0.x + v1.x) + (v2.x + v3.x);
            acc.y += (v0.y + v1.y) + (v2.y + v3.y);
            acc.z += (v0.z + v1.z) + (v2.z + v3.z);
            acc.w += (v0.w + v1.w) + (v2.w + v3.w);
        }
    }
    for (; j < cnt; j++) {
        int s = g_csr[start + j];
        float4 v = *(const float4*)(hb + (size_t)s * NH);
        if (EDGE_DINV) {
            float w = g_dinv[s];
            acc.x = fmaf(v.x, w, acc.x);
            acc.y = fmaf(v.y, w, acc.y);
            acc.z = fmaf(v.z, w, acc.z);
            acc.w = fmaf(v.w, w, acc.w);
        } else {
            acc.x += v.x; acc.y += v.y; acc.z += v.z; acc.w += v.w;
        }
    }

    int c = lane * 4;
    acc.x = fmaxf(fmaf(acc.x, dd, bias[c + 0]), 0.0f);
    acc.y = fmaxf(fmaf(acc.y, dd, bias[c + 1]), 0.0f);
    acc.z = fmaxf(fmaf(acc.z, dd, bias[c + 2]), 0.0f);
    acc.w = fmaxf(fmaf(acc.w, dd, bias[c + 3]), 0.0f);
    *(float4*)(out + (size_t)node * NH + c) = acc;
}

// ---------------- Launch ----------------
extern "C" void kernel_launch(void* const* d_in, const int* in_sizes, int n_in,
                              void* d_out, int out_size) {
    const float* x       = (const float*)d_in[0];
    const void*  ei      = d_in[1];
    const float* W1      = (const float*)d_in[2];
    const float* b1      = (const float*)d_in[3];
    const float* W2      = (const float*)d_in[4];
    const float* b2      = (const float*)d_in[5];
    const float* Wc      = (const float*)d_in[6];
    const float* bc      = (const float*)d_in[7];
    float* out           = (float*)d_out;

    const int N = in_sizes[0] / NF;       // 100000
    const int E = in_sizes[1] / 2;        // 1600000
    const int nb = (N + 1023) / 1024;

    // Node halves (H0 multiple of 128 for clean GEMM row blocks)
    const int H0 = ((N / 2) + 127) & ~127;    // 50048
    const int H1 = N - H0;                    // 49952

    // One-time side-stream + events (created on the uncaptured correctness
    // call; reused — and recorded as graph fork/join — on the capture call).
    static cudaStream_t s_side = nullptr;
    static cudaEvent_t  ev[6] = {};
    if (s_side == nullptr) {
        cudaStreamCreateWithFlags(&s_side, cudaStreamNonBlocking);
        for (int i = 0; i < 6; i++)
            cudaEventCreateWithFlags(&ev[i], cudaEventDisableTiming);
    }
    cudaEvent_t ev_fork = ev[0], ev_g1 = ev[1], ev_csr = ev[2];
    cudaEvent_t ev_s1 = ev[3], ev_g2 = ev[4], ev_s2 = ev[5];

    auto agg_blocks = [](int cnt) { return (int)(((long long)cnt * 32 + 255) / 256); };
    auto gy = [](int cnt) { return (unsigned)((cnt + 127) / 128); };

    // ---- Fork: GEMM1 (full, no dinv dependence) overlaps the CSR build ----
    cudaEventRecord(ev_fork, 0);
    cudaStreamWaitEvent(s_side, ev_fork, 0);
    {
        dim3 grid(1, gy(N));
        sgemm2<NF, false><<<grid, 256, 0, s_side>>>(x, -1, W1, 0, 0, N);
    }
    cudaEventRecord(ev_g1, s_side);

    // ---- CSR build on the main stream (overlapped with GEMM1) ----
    k_detect_dtype<<<1, 256>>>((const long long*)ei);
    k_zero_deg<<<(N + 1023) / 1024, 1024>>>(N);
    k_count_deg<<<(E + 511) / 512, 512>>>(ei, E);
    k_scan_blocks<<<nb, 1024>>>(N);
    k_scan_sums<<<1, 128>>>(nb);
    k_scan_add<<<nb, 1024>>>(N);
    k_fill_csr<<<(E + 511) / 512, 512>>>(ei, E);
    cudaEventRecord(ev_csr, 0);

    // ---- Pipelined layer boundary 1 ----
    // main: agg1_h0 -> GEMM2_h0            (needs GEMM1 + CSR)
    // side: agg1_h1 (|| GEMM2_h0)          (needs GEMM1 [in side order] + CSR)
    cudaStreamWaitEvent(0, ev_g1, 0);
    k_aggregate<true><<<agg_blocks(H0), 256>>>(0, b1, 1, 0, H0);
    cudaStreamWaitEvent(s_side, ev_csr, 0);
    k_aggregate<true><<<agg_blocks(H1), 256, 0, s_side>>>(0, b1, 1, H0, H1);
    cudaEventRecord(ev_s1, s_side);
    {
        dim3 grid(1, gy(H0));
        sgemm2<NH, true><<<grid, 256>>>(nullptr, 1, W2, 0, 0, N);
    }
    cudaStreamWaitEvent(0, ev_s1, 0);
    {
        dim3 grid(1, gy(H1));
        sgemm2<NH, true><<<grid, 256>>>(nullptr, 1, W2, 0, H0, N);
    }
    cudaEventRecord(ev_g2, 0);

    // ---- Pipelined layer boundary 2 ----
    // main: agg2_h0 -> cls_h0              (needs full GEMM2)
    // side: agg2_h1 (|| cls_h0)            (needs full GEMM2 via ev_g2)
    k_aggregate<false><<<agg_blocks(H0), 256>>>(0, b2, 1, 0, H0);
    cudaStreamWaitEvent(s_side, ev_g2, 0);
    k_aggregate<false><<<agg_blocks(H1), 256, 0, s_side>>>(0, b2, 1, H0, H1);
    cudaEventRecord(ev_s2, s_side);
    {
        dim3 grid(1, gy(H0));
        sgemm<128, 40, 32, 4, 8><<<grid, 160>>>(1, Wc, out, bc, 0, N, NC, NH);
    }
    cudaStreamWaitEvent(0, ev_s2, 0);
    {
        dim3 grid(1, gy(H1));
        sgemm<128, 40, 32, 4, 8><<<grid, 160>>>(1, Wc, out, bc, H0, N, NC, NH);
    }
}